// round 2
// baseline (speedup 1.0000x reference)
#include <cuda_runtime.h>
#include <cstdint>

// ---------------- problem constants ----------------
#define NS      524288
#define NEXP    16
#define HID     256
#define OUTD    3

// ---------------- tiling ----------------
#define TPB     256                 // threads per block (compute + sort kernels)
#define SPT     4                   // samples per thread in compute kernel
#define SPB     (TPB * SPT)         // 1024 samples per compute block (pad granule)
#define NBLK_C  (NS / SPB)          // 512
#define MAXBLK  (NBLK_C + NEXP)     // 528 upper bound incl. padding
#define HBLOCKS 256
#define HSPT    8                   // 256 blk * 256 thr * 8 = 524288

typedef unsigned long long u64;

// ---------------- device scratch (no cudaMalloc allowed) ----------------
__device__ float4 g_sorted[NS + NEXP * SPB];   // (x0, x1, bitcast(orig idx), pad)
__device__ int    g_counts[NEXP];
__device__ int    g_cursor[NEXP];              // atomic scatter cursors
__device__ int    g_end[NEXP];                 // region end (off + count) per expert
__device__ int    g_bmap[MAXBLK];              // compute-block -> expert (-1 = idle)
__device__ float  g_w[NEXP][6][HID];           // rows: w1r0, w1r1, b1, w2c0, w2c1, w2c2

// ---------------- helpers ----------------
__device__ __forceinline__ int expert_of(float x0, float x1) {
    int i = (int)floorf(x0 * 4.0f);
    int j = (int)floorf(x1 * 4.0f);
    i = max(0, min(3, i));
    j = max(0, min(3, j));
    return j * 4 + i;
}

__device__ __forceinline__ u64 f2fma(u64 a, u64 b, u64 c) {
    u64 d;
    asm("fma.rn.f32x2 %0, %1, %2, %3;" : "=l"(d) : "l"(a), "l"(b), "l"(c));
    return d;
}
__device__ __forceinline__ u64 f2pack(float lo, float hi) {
    u64 d;
    asm("mov.b64 %0, {%1, %2};" : "=l"(d) : "f"(lo), "f"(hi));
    return d;
}
__device__ __forceinline__ float2 f2unpack(u64 v) {
    float2 r;
    asm("mov.b64 {%0, %1}, %2;" : "=f"(r.x), "=f"(r.y) : "l"(v));
    return r;
}
__device__ __forceinline__ u64 f2relu(u64 v) {
    float2 r = f2unpack(v);
    return f2pack(fmaxf(r.x, 0.0f), fmaxf(r.y, 0.0f));
}

// ---------------- K0: repack weights column-major-ish + zero counters ----------------
__global__ void k_prep(const float* __restrict__ W1, const float* __restrict__ b1,
                       const float* __restrict__ W2) {
    int e = blockIdx.x, h = threadIdx.x;
    g_w[e][0][h] = W1[e * 2 * HID + h];             // W1[e][0][h]
    g_w[e][1][h] = W1[e * 2 * HID + HID + h];       // W1[e][1][h]
    g_w[e][2][h] = b1[e * HID + h];
    g_w[e][3][h] = W2[(e * HID + h) * OUTD + 0];
    g_w[e][4][h] = W2[(e * HID + h) * OUTD + 1];
    g_w[e][5][h] = W2[(e * HID + h) * OUTD + 2];
    if (e == 0 && h < NEXP) g_counts[h] = 0;        // reset for graph replay
}

// ---------------- K1: histogram ----------------
__global__ void __launch_bounds__(TPB) k_hist(const float2* __restrict__ s) {
    __shared__ int sc[NEXP];
    int tid = threadIdx.x;
    if (tid < NEXP) sc[tid] = 0;
    __syncthreads();
    int base = blockIdx.x * (TPB * HSPT);
    #pragma unroll
    for (int t = 0; t < HSPT; t++) {
        float2 xy = s[base + t * TPB + tid];
        atomicAdd(&sc[expert_of(xy.x, xy.y)], 1);
    }
    __syncthreads();
    if (tid < NEXP) atomicAdd(&g_counts[tid], sc[tid]);
}

// ---------------- K2: padded exclusive scan + block map ----------------
__global__ void k_scan() {
    __shared__ int s_off[NEXP], s_end[NEXP];
    if (threadIdx.x == 0) {
        int o = 0;
        for (int e = 0; e < NEXP; e++) {
            int c = g_counts[e];
            s_off[e] = o;
            s_end[e] = o + c;
            g_cursor[e] = o;
            g_end[e]    = o + c;
            o = (o + c + SPB - 1) / SPB * SPB;      // pad to block granule
        }
    }
    __syncthreads();
    for (int b = threadIdx.x; b < MAXBLK; b += blockDim.x) {
        int m = -1;
        #pragma unroll
        for (int e = 0; e < NEXP; e++)
            if (b * SPB >= s_off[e] && b * SPB < s_end[e]) m = e;
        g_bmap[b] = m;
    }
}

// ---------------- K3: scatter into expert-sorted buffer ----------------
__global__ void __launch_bounds__(TPB) k_scatter(const float2* __restrict__ s) {
    __shared__ int sc[NEXP], sb[NEXP], sr[NEXP];
    int tid = threadIdx.x;
    if (tid < NEXP) { sc[tid] = 0; sr[tid] = 0; }
    __syncthreads();
    int base = blockIdx.x * (TPB * HSPT);
    float2 xy[HSPT]; int e[HSPT];
    #pragma unroll
    for (int t = 0; t < HSPT; t++) {
        xy[t] = s[base + t * TPB + tid];
        e[t] = expert_of(xy[t].x, xy[t].y);
        atomicAdd(&sc[e[t]], 1);
    }
    __syncthreads();
    if (tid < NEXP) sb[tid] = atomicAdd(&g_cursor[tid], sc[tid]);
    __syncthreads();
    #pragma unroll
    for (int t = 0; t < HSPT; t++) {
        int r   = atomicAdd(&sr[e[t]], 1);
        int idx = base + t * TPB + tid;
        g_sorted[sb[e[t]] + r] = make_float4(xy[t].x, xy[t].y, __int_as_float(idx), 0.0f);
    }
}

// ---------------- K4: expert-uniform fused MLP (f32x2 packed over hidden pairs) ----------------
__global__ void __launch_bounds__(TPB) k_mlp(const float* __restrict__ b2,
                                             float* __restrict__ out) {
    int e = g_bmap[blockIdx.x];
    if (e < 0) return;

    __shared__ float sw[6 * HID];
    {
        const float4* src = (const float4*)(&g_w[e][0][0]);
        float4* dst = (float4*)sw;
        #pragma unroll
        for (int i = threadIdx.x; i < 6 * HID / 4; i += TPB) dst[i] = src[i];
    }
    int rend = g_end[e];
    __syncthreads();

    u64 xx0[SPT], xx1[SPT]; int idx[SPT]; bool valid[SPT];
    int base = blockIdx.x * SPB + threadIdx.x;
    #pragma unroll
    for (int t = 0; t < SPT; t++) {
        int slot = base + t * TPB;
        valid[t] = slot < rend;
        float4 sm = g_sorted[valid[t] ? slot : 0];
        xx0[t] = f2pack(sm.x, sm.x);
        xx1[t] = f2pack(sm.y, sm.y);
        idx[t] = __float_as_int(sm.z);
    }

    u64 acc0[SPT], acc1[SPT], acc2[SPT];
    #pragma unroll
    for (int t = 0; t < SPT; t++) { acc0[t] = 0ull; acc1[t] = 0ull; acc2[t] = 0ull; }

    const u64* w0p = (const u64*)(sw + 0 * HID);
    const u64* w1p = (const u64*)(sw + 1 * HID);
    const u64* bbp = (const u64*)(sw + 2 * HID);
    const u64* v0p = (const u64*)(sw + 3 * HID);
    const u64* v1p = (const u64*)(sw + 4 * HID);
    const u64* v2p = (const u64*)(sw + 5 * HID);

    // Each p handles hidden units (2p, 2p+1) packed into the two f32x2 lanes.
    #pragma unroll 4
    for (int p = 0; p < HID / 2; p++) {
        u64 w0 = w0p[p], w1 = w1p[p], bb = bbp[p];
        u64 v0 = v0p[p], v1 = v1p[p], v2 = v2p[p];
        #pragma unroll
        for (int t = 0; t < SPT; t++) {
            u64 h = f2fma(xx0[t], w0, f2fma(xx1[t], w1, bb));
            h = f2relu(h);
            acc0[t] = f2fma(h, v0, acc0[t]);
            acc1[t] = f2fma(h, v1, acc1[t]);
            acc2[t] = f2fma(h, v2, acc2[t]);
        }
    }

    float c0 = __ldg(&b2[e * 3 + 0]);
    float c1 = __ldg(&b2[e * 3 + 1]);
    float c2 = __ldg(&b2[e * 3 + 2]);
    #pragma unroll
    for (int t = 0; t < SPT; t++) {
        if (!valid[t]) continue;
        float2 a0 = f2unpack(acc0[t]);
        float2 a1 = f2unpack(acc1[t]);
        float2 a2 = f2unpack(acc2[t]);
        float* o = out + (size_t)idx[t] * 3;
        o[0] = a0.x + a0.y + c0;
        o[1] = a1.x + a1.y + c1;
        o[2] = a2.x + a2.y + c2;
    }
}

// ---------------- launch ----------------
extern "C" void kernel_launch(void* const* d_in, const int* in_sizes, int n_in,
                              void* d_out, int out_size) {
    const float* samples = (const float*)d_in[0];
    const float* W1      = (const float*)d_in[1];
    const float* b1      = (const float*)d_in[2];
    const float* W2      = (const float*)d_in[3];
    const float* b2      = (const float*)d_in[4];
    float* out           = (float*)d_out;

    k_prep<<<NEXP, HID>>>(W1, b1, W2);
    k_hist<<<HBLOCKS, TPB>>>((const float2*)samples);
    k_scan<<<1, 256>>>();
    k_scatter<<<HBLOCKS, TPB>>>((const float2*)samples);
    k_mlp<<<MAXBLK, TPB>>>(b2, out);
}

// round 3
// speedup vs baseline: 1.0259x; 1.0259x over previous
#include <cuda_runtime.h>
#include <cstdint>

// ---------------- problem constants ----------------
#define NS      524288
#define NEXP    16
#define HID     256
#define OUTD    3

// ---------------- tiling ----------------
#define TPB     256                 // threads per block (compute kernel)
#define SPT     4                   // samples per thread in compute kernel
#define SPB     (TPB * SPT)         // 1024 samples per compute block (tile granule)
#define MAXBLK  ((NS / SPB) + NEXP) // 528 upper bound on tiles
#define SBLK    512                 // scatter blocks
#define SSPT    4                   // 512 * 256 * 4 = 524288
#define CAP     NS                  // per-expert region capacity (worst case)
#define CSTRIDE 32                  // cursor padding (ints) -> 128B apart

typedef unsigned long long u64;

// ---------------- device scratch (static, no allocs) ----------------
__device__ float4 g_big[NEXP * CAP];           // expert-partitioned (x,y,idx,pad)
__device__ int    g_cursor[NEXP * CSTRIDE];    // padded global cursors
__device__ int    g_done;                      // scatter completion ticket
__device__ int    g_cnt[NEXP];                 // final per-expert counts
__device__ int    g_bmap[MAXBLK];              // tile -> (expert<<16 | tile_in_expert), -1 idle
__device__ float  g_w[NEXP][6][HID];           // w1r0, w1r1, b1, w2c0, w2c1, w2c2

// ---------------- helpers ----------------
__device__ __forceinline__ int expert_of(float x0, float x1) {
    int i = (int)floorf(x0 * 4.0f);
    int j = (int)floorf(x1 * 4.0f);
    i = max(0, min(3, i));
    j = max(0, min(3, j));
    return j * 4 + i;
}
__device__ __forceinline__ u64 f2fma(u64 a, u64 b, u64 c) {
    u64 d;
    asm("fma.rn.f32x2 %0, %1, %2, %3;" : "=l"(d) : "l"(a), "l"(b), "l"(c));
    return d;
}
__device__ __forceinline__ u64 f2pack(float lo, float hi) {
    u64 d;
    asm("mov.b64 %0, {%1, %2};" : "=l"(d) : "f"(lo), "f"(hi));
    return d;
}
__device__ __forceinline__ float2 f2unpack(u64 v) {
    float2 r;
    asm("mov.b64 {%0, %1}, %2;" : "=f"(r.x), "=f"(r.y) : "l"(v));
    return r;
}
__device__ __forceinline__ u64 f2relu(u64 v) {
    float2 r = f2unpack(v);
    return f2pack(fmaxf(r.x, 0.0f), fmaxf(r.y, 0.0f));
}

// ---------------- K0: weight repack + per-replay state reset ----------------
__global__ void k_prep(const float* __restrict__ W1, const float* __restrict__ b1,
                       const float* __restrict__ W2) {
    int e = blockIdx.x, h = threadIdx.x;
    g_w[e][0][h] = W1[e * 2 * HID + h];
    g_w[e][1][h] = W1[e * 2 * HID + HID + h];
    g_w[e][2][h] = b1[e * HID + h];
    g_w[e][3][h] = W2[(e * HID + h) * OUTD + 0];
    g_w[e][4][h] = W2[(e * HID + h) * OUTD + 1];
    g_w[e][5][h] = W2[(e * HID + h) * OUTD + 2];
    if (e == 0) {
        if (h < NEXP) g_cursor[h * CSTRIDE] = h * CAP;
        if (h == NEXP) g_done = 0;
    }
}

// ---------------- K1: single-pass expert scatter + tile-map build ----------------
__global__ void __launch_bounds__(TPB) k_scatter(const float2* __restrict__ s) {
    __shared__ int sc[NEXP], sb[NEXP], sr[NEXP];
    int tid  = threadIdx.x;
    int lane = tid & 31;
    unsigned lt_mask = (1u << lane) - 1u;

    if (tid < NEXP) { sc[tid] = 0; sr[tid] = 0; }
    __syncthreads();

    int base = blockIdx.x * (TPB * SSPT);
    float2 xy[SSPT]; int e[SSPT];

    // Phase 1: block histogram (warp-aggregated)
    #pragma unroll
    for (int t = 0; t < SSPT; t++) {
        xy[t] = s[base + t * TPB + tid];
        e[t]  = expert_of(xy[t].x, xy[t].y);
        unsigned m = __match_any_sync(0xffffffffu, e[t]);
        if ((__ffs(m) - 1) == lane) atomicAdd(&sc[e[t]], __popc(m));
    }
    __syncthreads();

    // Grab per-expert global cursor ranges (padded addresses)
    if (tid < NEXP) sb[tid] = atomicAdd(&g_cursor[tid * CSTRIDE], sc[tid]);
    __syncthreads();

    // Phase 2: ranked scatter (warp-aggregated)
    #pragma unroll
    for (int t = 0; t < SSPT; t++) {
        unsigned m   = __match_any_sync(0xffffffffu, e[t]);
        int leader   = __ffs(m) - 1;
        int rank     = __popc(m & lt_mask);
        int wbase    = 0;
        if (lane == leader) wbase = atomicAdd(&sr[e[t]], __popc(m));
        wbase = __shfl_sync(0xffffffffu, wbase, leader);
        int idx = base + t * TPB + tid;
        g_big[sb[e[t]] + wbase + rank] =
            make_float4(xy[t].x, xy[t].y, __int_as_float(idx), 0.0f);
    }

    // Last block builds the tile map
    __threadfence();
    __syncthreads();
    __shared__ int is_last;
    if (tid == 0) is_last = (atomicAdd(&g_done, 1) == gridDim.x - 1) ? 1 : 0;
    __syncthreads();
    if (!is_last) return;

    __shared__ int cnt[NEXP], toff[NEXP + 1];
    if (tid < NEXP) cnt[tid] = g_cursor[tid * CSTRIDE] - tid * CAP;
    __syncthreads();
    if (tid == 0) {
        int o = 0;
        for (int ee = 0; ee < NEXP; ee++) {
            toff[ee] = o;
            o += (cnt[ee] + SPB - 1) / SPB;
        }
        toff[NEXP] = o;
    }
    __syncthreads();
    for (int b = tid; b < MAXBLK; b += TPB) g_bmap[b] = -1;
    if (tid < NEXP) g_cnt[tid] = cnt[tid];
    __syncthreads();
    if (tid < NEXP) {
        int ntile = toff[tid + 1] - toff[tid];
        for (int t = 0; t < ntile; t++)
            g_bmap[toff[tid] + t] = (tid << 16) | t;
    }
}

// ---------------- K2: expert-uniform fused MLP (f32x2 over hidden pairs) ----------------
__global__ void __launch_bounds__(TPB) k_mlp(const float* __restrict__ b2,
                                             float* __restrict__ out) {
    int v = g_bmap[blockIdx.x];
    if (v < 0) return;
    int e    = v >> 16;
    int tile = v & 0xffff;

    __shared__ float sw[6 * HID];
    {
        const float4* src = (const float4*)(&g_w[e][0][0]);
        float4* dst = (float4*)sw;
        #pragma unroll
        for (int i = threadIdx.x; i < 6 * HID / 4; i += TPB) dst[i] = src[i];
    }
    int rbase = e * CAP + tile * SPB;
    int rend  = e * CAP + g_cnt[e];
    __syncthreads();

    u64 xx0[SPT], xx1[SPT]; int idx[SPT]; bool valid[SPT];
    #pragma unroll
    for (int t = 0; t < SPT; t++) {
        int slot = rbase + t * TPB + threadIdx.x;
        valid[t] = slot < rend;
        float4 sm = g_big[valid[t] ? slot : rbase];
        xx0[t] = f2pack(sm.x, sm.x);
        xx1[t] = f2pack(sm.y, sm.y);
        idx[t] = __float_as_int(sm.z);
    }

    u64 acc0[SPT], acc1[SPT], acc2[SPT];
    #pragma unroll
    for (int t = 0; t < SPT; t++) { acc0[t] = 0ull; acc1[t] = 0ull; acc2[t] = 0ull; }

    const u64* w0p = (const u64*)(sw + 0 * HID);
    const u64* w1p = (const u64*)(sw + 1 * HID);
    const u64* bbp = (const u64*)(sw + 2 * HID);
    const u64* v0p = (const u64*)(sw + 3 * HID);
    const u64* v1p = (const u64*)(sw + 4 * HID);
    const u64* v2p = (const u64*)(sw + 5 * HID);

    #pragma unroll 4
    for (int p = 0; p < HID / 2; p++) {
        u64 w0 = w0p[p], w1 = w1p[p], bb = bbp[p];
        u64 v0 = v0p[p], v1 = v1p[p], v2 = v2p[p];
        #pragma unroll
        for (int t = 0; t < SPT; t++) {
            u64 h = f2fma(xx0[t], w0, f2fma(xx1[t], w1, bb));
            h = f2relu(h);
            acc0[t] = f2fma(h, v0, acc0[t]);
            acc1[t] = f2fma(h, v1, acc1[t]);
            acc2[t] = f2fma(h, v2, acc2[t]);
        }
    }

    float c0 = __ldg(&b2[e * 3 + 0]);
    float c1 = __ldg(&b2[e * 3 + 1]);
    float c2 = __ldg(&b2[e * 3 + 2]);
    #pragma unroll
    for (int t = 0; t < SPT; t++) {
        if (!valid[t]) continue;
        float2 a0 = f2unpack(acc0[t]);
        float2 a1 = f2unpack(acc1[t]);
        float2 a2 = f2unpack(acc2[t]);
        float* o = out + (size_t)idx[t] * 3;
        o[0] = a0.x + a0.y + c0;
        o[1] = a1.x + a1.y + c1;
        o[2] = a2.x + a2.y + c2;
    }
}

// ---------------- launch ----------------
extern "C" void kernel_launch(void* const* d_in, const int* in_sizes, int n_in,
                              void* d_out, int out_size) {
    const float* samples = (const float*)d_in[0];
    const float* W1      = (const float*)d_in[1];
    const float* b1      = (const float*)d_in[2];
    const float* W2      = (const float*)d_in[3];
    const float* b2      = (const float*)d_in[4];
    float* out           = (float*)d_out;

    k_prep<<<NEXP, HID>>>(W1, b1, W2);
    k_scatter<<<SBLK, TPB>>>((const float2*)samples);
    k_mlp<<<MAXBLK, TPB>>>(b2, out);
}

// round 4
// speedup vs baseline: 1.0374x; 1.0112x over previous
#include <cuda_runtime.h>
#include <cstdint>

// ---------------- problem constants ----------------
#define NS      524288
#define NEXP    16
#define HID     256
#define OUTD    3

// ---------------- tiling ----------------
#define TPB     256                 // threads per block (mlp)
#define SPT     4                   // samples per thread (mlp)
#define SPB     (TPB * SPT)         // 1024 samples per mlp tile
#define MAXBLK  ((NS / SPB) + NEXP) // 528 tiles upper bound
#define SBLK    512                 // scatter blocks
#define SSPT    4                   // 512 * 256 * 4 = 524288
#define CAP     NS                  // per-expert region capacity
#define CSTRIDE 32                  // cursor padding (128B apart)

typedef unsigned long long u64;

// ---------------- device scratch (static; zero-init is the "reset" state) ----------------
__device__ int g_sidx[NEXP * CAP];        // expert-partitioned original indices
__device__ int g_cur[NEXP * CSTRIDE];     // RELATIVE cursors (start at 0)
__device__ int g_done;                    // scatter completion ticket
__device__ int g_fin;                     // mlp completion ticket
__device__ int g_cnt[NEXP];               // per-expert counts
__device__ int g_bmap[MAXBLK];            // tile -> (expert<<16 | tile_in_expert), -1 idle

// ---------------- helpers ----------------
__device__ __forceinline__ int expert_of(float x0, float x1) {
    int i = (int)floorf(x0 * 4.0f);
    int j = (int)floorf(x1 * 4.0f);
    i = max(0, min(3, i));
    j = max(0, min(3, j));
    return j * 4 + i;
}
__device__ __forceinline__ u64 f2fma(u64 a, u64 b, u64 c) {
    u64 d;
    asm("fma.rn.f32x2 %0, %1, %2, %3;" : "=l"(d) : "l"(a), "l"(b), "l"(c));
    return d;
}
__device__ __forceinline__ u64 f2pack(float lo, float hi) {
    u64 d;
    asm("mov.b64 %0, {%1, %2};" : "=l"(d) : "f"(lo), "f"(hi));
    return d;
}
__device__ __forceinline__ float2 f2unpack(u64 v) {
    float2 r;
    asm("mov.b64 {%0, %1}, %2;" : "=f"(r.x), "=f"(r.y) : "l"(v));
    return r;
}
__device__ __forceinline__ u64 f2relu(u64 v) {
    float2 r = f2unpack(v);
    return f2pack(fmaxf(r.x, 0.0f), fmaxf(r.y, 0.0f));
}

// ---------------- K1: single-pass expert scatter (index-only) + tile map ----------------
__global__ void __launch_bounds__(256) k_scatter(const float2* __restrict__ s) {
    __shared__ int sc[NEXP], sb[NEXP], sr[NEXP];
    int tid  = threadIdx.x;
    int lane = tid & 31;
    unsigned lt_mask = (1u << lane) - 1u;

    if (tid < NEXP) { sc[tid] = 0; sr[tid] = 0; }
    __syncthreads();

    int base = blockIdx.x * (256 * SSPT);
    int e[SSPT];

    // Phase 1: block histogram (warp-aggregated)
    #pragma unroll
    for (int t = 0; t < SSPT; t++) {
        float2 xy = s[base + t * 256 + tid];
        e[t] = expert_of(xy.x, xy.y);
        unsigned m = __match_any_sync(0xffffffffu, e[t]);
        if ((__ffs(m) - 1) == lane) atomicAdd(&sc[e[t]], __popc(m));
    }
    __syncthreads();

    if (tid < NEXP) sb[tid] = atomicAdd(&g_cur[tid * CSTRIDE], sc[tid]);
    __syncthreads();

    // Phase 2: ranked scatter (warp-aggregated) — indices only
    #pragma unroll
    for (int t = 0; t < SSPT; t++) {
        unsigned m = __match_any_sync(0xffffffffu, e[t]);
        int leader = __ffs(m) - 1;
        int rank   = __popc(m & lt_mask);
        int wbase  = 0;
        if (lane == leader) wbase = atomicAdd(&sr[e[t]], __popc(m));
        wbase = __shfl_sync(0xffffffffu, wbase, leader);
        g_sidx[e[t] * CAP + sb[e[t]] + wbase + rank] = base + t * 256 + tid;
    }

    // Last block builds tile map
    __threadfence();
    __syncthreads();
    __shared__ int is_last;
    if (tid == 0) is_last = (atomicAdd(&g_done, 1) == gridDim.x - 1) ? 1 : 0;
    __syncthreads();
    if (!is_last) return;

    __shared__ int cnt[NEXP], toff[NEXP + 1];
    if (tid < NEXP) cnt[tid] = g_cur[tid * CSTRIDE];
    __syncthreads();
    if (tid == 0) {
        int o = 0;
        for (int ee = 0; ee < NEXP; ee++) {
            toff[ee] = o;
            o += (cnt[ee] + SPB - 1) / SPB;
        }
        toff[NEXP] = o;
    }
    __syncthreads();
    for (int b = tid; b < MAXBLK; b += 256) g_bmap[b] = -1;
    if (tid < NEXP) g_cnt[tid] = cnt[tid];
    __syncthreads();
    if (tid < NEXP) {
        int ntile = toff[tid + 1] - toff[tid];
        for (int t = 0; t < ntile; t++)
            g_bmap[toff[tid] + t] = (tid << 16) | t;
    }
}

// ---------------- K2: expert-uniform fused MLP (single wave, packed weights) ----------------
__global__ void __launch_bounds__(TPB, 4) k_mlp(const float2* __restrict__ s,
                                                const float* __restrict__ W1,
                                                const float* __restrict__ b1,
                                                const float* __restrict__ W2,
                                                const float* __restrict__ b2,
                                                float* __restrict__ out) {
    int v = g_bmap[blockIdx.x];
    // packed weights: per hidden pair p (12 floats = 6 u64):
    // [w0lo w0hi | w1lo w1hi | bblo bbhi | v0lo v0hi | v1lo v1hi | v2lo v2hi]
    __shared__ float sw[128 * 12];

    if (v >= 0) {
        int e    = v >> 16;
        int tile = v & 0xffff;

        if (threadIdx.x < 128) {
            int p = threadIdx.x;
            int h = 2 * p;
            sw[p * 12 + 0]  = W1[e * 512 + h];
            sw[p * 12 + 1]  = W1[e * 512 + h + 1];
            sw[p * 12 + 2]  = W1[e * 512 + 256 + h];
            sw[p * 12 + 3]  = W1[e * 512 + 256 + h + 1];
            sw[p * 12 + 4]  = b1[e * 256 + h];
            sw[p * 12 + 5]  = b1[e * 256 + h + 1];
            sw[p * 12 + 6]  = W2[(e * 256 + h) * 3 + 0];
            sw[p * 12 + 7]  = W2[(e * 256 + h + 1) * 3 + 0];
            sw[p * 12 + 8]  = W2[(e * 256 + h) * 3 + 1];
            sw[p * 12 + 9]  = W2[(e * 256 + h + 1) * 3 + 1];
            sw[p * 12 + 10] = W2[(e * 256 + h) * 3 + 2];
            sw[p * 12 + 11] = W2[(e * 256 + h + 1) * 3 + 2];
        }
        int rbase = e * CAP + tile * SPB;
        int rend  = e * CAP + g_cnt[e];
        __syncthreads();

        u64 xx0[SPT], xx1[SPT]; int idx[SPT];
        #pragma unroll
        for (int t = 0; t < SPT; t++) {
            int slot = rbase + t * TPB + threadIdx.x;
            idx[t] = (slot < rend) ? g_sidx[slot] : -1;
            float2 xy = __ldg(&s[(idx[t] >= 0) ? idx[t] : 0]);
            xx0[t] = f2pack(xy.x, xy.x);
            xx1[t] = f2pack(xy.y, xy.y);
        }

        u64 acc0[SPT], acc1[SPT], acc2[SPT];
        #pragma unroll
        for (int t = 0; t < SPT; t++) { acc0[t] = 0ull; acc1[t] = 0ull; acc2[t] = 0ull; }

        const ulonglong2* swq = (const ulonglong2*)sw;
        #pragma unroll 4
        for (int p = 0; p < 128; p++) {
            ulonglong2 q0 = swq[p * 3 + 0];   // w0, w1
            ulonglong2 q1 = swq[p * 3 + 1];   // bb, v0
            ulonglong2 q2 = swq[p * 3 + 2];   // v1, v2
            #pragma unroll
            for (int t = 0; t < SPT; t++) {
                u64 h = f2fma(xx0[t], q0.x, f2fma(xx1[t], q0.y, q1.x));
                h = f2relu(h);
                acc0[t] = f2fma(h, q1.y, acc0[t]);
                acc1[t] = f2fma(h, q2.x, acc1[t]);
                acc2[t] = f2fma(h, q2.y, acc2[t]);
            }
        }

        float c0 = __ldg(&b2[e * 3 + 0]);
        float c1 = __ldg(&b2[e * 3 + 1]);
        float c2 = __ldg(&b2[e * 3 + 2]);
        #pragma unroll
        for (int t = 0; t < SPT; t++) {
            if (idx[t] < 0) continue;
            float2 a0 = f2unpack(acc0[t]);
            float2 a1 = f2unpack(acc1[t]);
            float2 a2 = f2unpack(acc2[t]);
            float* o = out + (size_t)idx[t] * 3;
            o[0] = a0.x + a0.y + c0;
            o[1] = a1.x + a1.y + c1;
            o[2] = a2.x + a2.y + c2;
        }
    }

    // per-replay state reset: last block to finish clears cursors/tickets
    if (threadIdx.x == 0) {
        __threadfence();
        if (atomicAdd(&g_fin, 1) == (int)gridDim.x - 1) {
            g_fin  = 0;
            g_done = 0;
            #pragma unroll
            for (int ee = 0; ee < NEXP; ee++) g_cur[ee * CSTRIDE] = 0;
        }
    }
}

// ---------------- launch ----------------
extern "C" void kernel_launch(void* const* d_in, const int* in_sizes, int n_in,
                              void* d_out, int out_size) {
    const float* samples = (const float*)d_in[0];
    const float* W1      = (const float*)d_in[1];
    const float* b1      = (const float*)d_in[2];
    const float* W2      = (const float*)d_in[3];
    const float* b2      = (const float*)d_in[4];
    float* out           = (float*)d_out;

    k_scatter<<<SBLK, 256>>>((const float2*)samples);
    k_mlp<<<MAXBLK, TPB>>>((const float2*)samples, W1, b1, W2, b2, out);
}

// round 6
// speedup vs baseline: 1.0686x; 1.0301x over previous
#include <cuda_runtime.h>
#include <cstdint>

// ---------------- problem constants ----------------
#define NS      524288
#define NEXP    16
#define HID     256
#define OUTD    3

// ---------------- tiling ----------------
#define TPB     128                 // threads per block (mlp)
#define SPT     8                   // samples per thread (mlp)
#define SPB     (TPB * SPT)         // 1024 samples per mlp tile
#define MAXBLK  ((NS / SPB) + NEXP) // 528 tiles upper bound
#define SBLK    512                 // scatter blocks
#define SSPT    4                   // 512 * 256 * 4 = 524288
#define CAP     NS                  // per-expert region capacity
#define CSTRIDE 32                  // cursor padding (128B apart)

typedef unsigned long long u64;

// ---------------- device scratch (static; zero-init is the "reset" state) ----------------
__device__ int g_sidx[NEXP * CAP];        // expert-partitioned original indices
__device__ int g_cur[NEXP * CSTRIDE];     // RELATIVE cursors (start at 0)
__device__ int g_done;                    // scatter completion ticket
__device__ int g_fin;                     // mlp completion ticket
__device__ int g_cnt[NEXP];               // per-expert counts
__device__ int g_bmap[MAXBLK];            // tile -> (expert<<16 | tile_in_expert), -1 idle

// ---------------- helpers ----------------
__device__ __forceinline__ int expert_of(float x0, float x1) {
    int i = (int)floorf(x0 * 4.0f);
    int j = (int)floorf(x1 * 4.0f);
    i = max(0, min(3, i));
    j = max(0, min(3, j));
    return j * 4 + i;
}
__device__ __forceinline__ u64 f2fma(u64 a, u64 b, u64 c) {
    u64 d;
    asm("fma.rn.f32x2 %0, %1, %2, %3;" : "=l"(d) : "l"(a), "l"(b), "l"(c));
    return d;
}
__device__ __forceinline__ u64 f2pack(float lo, float hi) {
    u64 d;
    asm("mov.b64 %0, {%1, %2};" : "=l"(d) : "f"(lo), "f"(hi));
    return d;
}
__device__ __forceinline__ float2 f2unpack(u64 v) {
    float2 r;
    asm("mov.b64 {%0, %1}, %2;" : "=f"(r.x), "=f"(r.y) : "l"(v));
    return r;
}
__device__ __forceinline__ u64 f2relu(u64 v) {
    float2 r = f2unpack(v);
    return f2pack(fmaxf(r.x, 0.0f), fmaxf(r.y, 0.0f));
}

// ---------------- K1: single-pass expert scatter (index-only) + tile map ----------------
__global__ void __launch_bounds__(256) k_scatter(const float2* __restrict__ s) {
    __shared__ int sc[NEXP], sb[NEXP], sr[NEXP];
    int tid  = threadIdx.x;
    int lane = tid & 31;
    unsigned lt_mask = (1u << lane) - 1u;

    if (tid < NEXP) { sc[tid] = 0; sr[tid] = 0; }
    __syncthreads();

    int base = blockIdx.x * (256 * SSPT);
    int e[SSPT];

    // Phase 1: block histogram (warp-aggregated)
    #pragma unroll
    for (int t = 0; t < SSPT; t++) {
        float2 xy = s[base + t * 256 + tid];
        e[t] = expert_of(xy.x, xy.y);
        unsigned m = __match_any_sync(0xffffffffu, e[t]);
        if ((__ffs(m) - 1) == lane) atomicAdd(&sc[e[t]], __popc(m));
    }
    __syncthreads();

    if (tid < NEXP) sb[tid] = atomicAdd(&g_cur[tid * CSTRIDE], sc[tid]);
    __syncthreads();

    // Phase 2: ranked scatter (warp-aggregated) — indices only
    #pragma unroll
    for (int t = 0; t < SSPT; t++) {
        unsigned m = __match_any_sync(0xffffffffu, e[t]);
        int leader = __ffs(m) - 1;
        int rank   = __popc(m & lt_mask);
        int wbase  = 0;
        if (lane == leader) wbase = atomicAdd(&sr[e[t]], __popc(m));
        wbase = __shfl_sync(0xffffffffu, wbase, leader);
        g_sidx[e[t] * CAP + sb[e[t]] + wbase + rank] = base + t * 256 + tid;
    }

    // Last block builds tile map
    __threadfence();
    __syncthreads();
    __shared__ int is_last;
    if (tid == 0) is_last = (atomicAdd(&g_done, 1) == gridDim.x - 1) ? 1 : 0;
    __syncthreads();
    if (!is_last) return;

    __shared__ int cnt[NEXP], toff[NEXP + 1];
    if (tid < NEXP) cnt[tid] = g_cur[tid * CSTRIDE];
    __syncthreads();
    if (tid == 0) {
        int o = 0;
        for (int ee = 0; ee < NEXP; ee++) {
            toff[ee] = o;
            o += (cnt[ee] + SPB - 1) / SPB;
        }
        toff[NEXP] = o;
    }
    __syncthreads();
    for (int b = tid; b < MAXBLK; b += 256) g_bmap[b] = -1;
    if (tid < NEXP) g_cnt[tid] = cnt[tid];
    __syncthreads();
    if (tid < NEXP) {
        int ntile = toff[tid + 1] - toff[tid];
        for (int t = 0; t < ntile; t++)
            g_bmap[toff[tid] + t] = (tid << 16) | t;
    }
}

// ---------------- K2: expert-uniform fused MLP (8 chains/thread, packed weights) ----------------
__global__ void __launch_bounds__(TPB, 4) k_mlp(const float2* __restrict__ s,
                                                const float* __restrict__ W1,
                                                const float* __restrict__ b1,
                                                const float* __restrict__ W2,
                                                const float* __restrict__ b2,
                                                float* __restrict__ out) {
    int v = g_bmap[blockIdx.x];
    // packed weights: per hidden pair p (12 floats = 3 x ulonglong2):
    // [w0lo w0hi | w1lo w1hi | bblo bbhi | v0lo v0hi | v1lo v1hi | v2lo v2hi]
    __shared__ float sw[128 * 12];

    if (v >= 0) {
        int e    = v >> 16;
        int tile = v & 0xffff;

        {
            int p = threadIdx.x;   // TPB == 128 == number of hidden pairs
            int h = 2 * p;
            sw[p * 12 + 0]  = W1[e * 512 + h];
            sw[p * 12 + 1]  = W1[e * 512 + h + 1];
            sw[p * 12 + 2]  = W1[e * 512 + 256 + h];
            sw[p * 12 + 3]  = W1[e * 512 + 256 + h + 1];
            sw[p * 12 + 4]  = b1[e * 256 + h];
            sw[p * 12 + 5]  = b1[e * 256 + h + 1];
            sw[p * 12 + 6]  = W2[(e * 256 + h) * 3 + 0];
            sw[p * 12 + 7]  = W2[(e * 256 + h + 1) * 3 + 0];
            sw[p * 12 + 8]  = W2[(e * 256 + h) * 3 + 1];
            sw[p * 12 + 9]  = W2[(e * 256 + h + 1) * 3 + 1];
            sw[p * 12 + 10] = W2[(e * 256 + h) * 3 + 2];
            sw[p * 12 + 11] = W2[(e * 256 + h + 1) * 3 + 2];
        }
        int rbase = e * CAP + tile * SPB;
        int rend  = e * CAP + g_cnt[e];
        __syncthreads();

        u64 xx0[SPT], xx1[SPT];
        #pragma unroll
        for (int t = 0; t < SPT; t++) {
            int slot = rbase + t * TPB + threadIdx.x;
            int idx  = (slot < rend) ? g_sidx[slot] : 0;
            float2 xy = __ldg(&s[idx]);
            xx0[t] = f2pack(xy.x, xy.x);
            xx1[t] = f2pack(xy.y, xy.y);
        }

        u64 acc0[SPT], acc1[SPT], acc2[SPT];
        #pragma unroll
        for (int t = 0; t < SPT; t++) { acc0[t] = 0ull; acc1[t] = 0ull; acc2[t] = 0ull; }

        const ulonglong2* swq = (const ulonglong2*)sw;
        #pragma unroll 8
        for (int p = 0; p < 128; p++) {
            ulonglong2 q0 = swq[p * 3 + 0];   // w0, w1
            ulonglong2 q1 = swq[p * 3 + 1];   // bb, v0
            ulonglong2 q2 = swq[p * 3 + 2];   // v1, v2
            #pragma unroll
            for (int t = 0; t < SPT; t++) {
                u64 h = f2fma(xx0[t], q0.x, f2fma(xx1[t], q0.y, q1.x));
                h = f2relu(h);
                acc0[t] = f2fma(h, q1.y, acc0[t]);
                acc1[t] = f2fma(h, q2.x, acc1[t]);
                acc2[t] = f2fma(h, q2.y, acc2[t]);
            }
        }

        float c0 = __ldg(&b2[e * 3 + 0]);
        float c1 = __ldg(&b2[e * 3 + 1]);
        float c2 = __ldg(&b2[e * 3 + 2]);
        #pragma unroll
        for (int t = 0; t < SPT; t++) {
            int slot = rbase + t * TPB + threadIdx.x;
            if (slot >= rend) continue;
            int idx = g_sidx[slot];           // L1 hit (read in prologue)
            float2 a0 = f2unpack(acc0[t]);
            float2 a1 = f2unpack(acc1[t]);
            float2 a2 = f2unpack(acc2[t]);
            float* o = out + (size_t)idx * 3;
            o[0] = a0.x + a0.y + c0;
            o[1] = a1.x + a1.y + c1;
            o[2] = a2.x + a2.y + c2;
        }
    }

    // per-replay state reset: last block to finish clears cursors/tickets
    if (threadIdx.x == 0) {
        __threadfence();
        if (atomicAdd(&g_fin, 1) == (int)gridDim.x - 1) {
            g_fin  = 0;
            g_done = 0;
            #pragma unroll
            for (int ee = 0; ee < NEXP; ee++) g_cur[ee * CSTRIDE] = 0;
        }
    }
}

// ---------------- launch ----------------
extern "C" void kernel_launch(void* const* d_in, const int* in_sizes, int n_in,
                              void* d_out, int out_size) {
    const float* samples = (const float*)d_in[0];
    const float* W1      = (const float*)d_in[1];
    const float* b1      = (const float*)d_in[2];
    const float* W2      = (const float*)d_in[3];
    const float* b2      = (const float*)d_in[4];
    float* out           = (float*)d_out;

    k_scatter<<<SBLK, 256>>>((const float2*)samples);
    k_mlp<<<MAXBLK, TPB>>>((const float2*)samples, W1, b1, W2, b2, out);
}

// round 9
// speedup vs baseline: 1.0832x; 1.0137x over previous
#include <cuda_runtime.h>
#include <cstdint>

// ---------------- problem constants ----------------
#define NS      524288
#define NEXP    16
#define HID     256
#define OUTD    3

// ---------------- tiling ----------------
#define TPB     128                 // threads per block (mlp)
#define SPT     8                   // samples per thread (mlp)
#define SPB     (TPB * SPT)         // 1024 samples per mlp tile
#define MAXBLK  ((NS / SPB) + NEXP) // 528 tiles upper bound
#define SBLK    512                 // scatter blocks
#define SSPT    4                   // 512 * 256 * 4 = 524288
#define CAP     NS                  // per-expert region capacity
#define CSTRIDE 32                  // cursor padding (128B apart)

typedef unsigned long long u64;

// ---------------- device scratch (static; zero-init is the "reset" state) ----------------
__device__ int g_sidx[NEXP * CAP];        // expert-partitioned original indices
__device__ int g_cur[NEXP * CSTRIDE];     // RELATIVE cursors (start at 0)
__device__ int g_done;                    // scatter completion ticket
__device__ int g_fin;                     // mlp completion ticket
__device__ int g_cnt[NEXP];               // per-expert counts
__device__ int g_bmap[MAXBLK];            // tile -> (expert<<16 | tile_in_expert), -1 idle

// ---------------- helpers ----------------
__device__ __forceinline__ int expert_of(float x0, float x1) {
    int i = (int)floorf(x0 * 4.0f);
    int j = (int)floorf(x1 * 4.0f);
    i = max(0, min(3, i));
    j = max(0, min(3, j));
    return j * 4 + i;
}
__device__ __forceinline__ u64 f2fma(u64 a, u64 b, u64 c) {
    u64 d;
    asm("fma.rn.f32x2 %0, %1, %2, %3;" : "=l"(d) : "l"(a), "l"(b), "l"(c));
    return d;
}
__device__ __forceinline__ u64 f2pack(float lo, float hi) {
    u64 d;
    asm("mov.b64 %0, {%1, %2};" : "=l"(d) : "f"(lo), "f"(hi));
    return d;
}
__device__ __forceinline__ float2 f2unpack(u64 v) {
    float2 r;
    asm("mov.b64 {%0, %1}, %2;" : "=f"(r.x), "=f"(r.y) : "l"(v));
    return r;
}
__device__ __forceinline__ u64 f2relu(u64 v) {
    float2 r = f2unpack(v);
    return f2pack(fmaxf(r.x, 0.0f), fmaxf(r.y, 0.0f));
}

// ---------------- K1: single-pass expert scatter (index-only) + tile map ----------------
__global__ void __launch_bounds__(256) k_scatter(const float2* __restrict__ s) {
    __shared__ int sc[NEXP], sb[NEXP], sr[NEXP];
    int tid  = threadIdx.x;
    int lane = tid & 31;
    unsigned lt_mask = (1u << lane) - 1u;

    if (tid < NEXP) { sc[tid] = 0; sr[tid] = 0; }
    __syncthreads();

    int base = blockIdx.x * (256 * SSPT);
    int e[SSPT];

    // Phase 1: block histogram (warp-aggregated)
    #pragma unroll
    for (int t = 0; t < SSPT; t++) {
        float2 xy = s[base + t * 256 + tid];
        e[t] = expert_of(xy.x, xy.y);
        unsigned m = __match_any_sync(0xffffffffu, e[t]);
        if ((__ffs(m) - 1) == lane) atomicAdd(&sc[e[t]], __popc(m));
    }
    __syncthreads();

    if (tid < NEXP) sb[tid] = atomicAdd(&g_cur[tid * CSTRIDE], sc[tid]);
    __syncthreads();

    // Phase 2: ranked scatter (warp-aggregated) — indices only
    #pragma unroll
    for (int t = 0; t < SSPT; t++) {
        unsigned m = __match_any_sync(0xffffffffu, e[t]);
        int leader = __ffs(m) - 1;
        int rank   = __popc(m & lt_mask);
        int wbase  = 0;
        if (lane == leader) wbase = atomicAdd(&sr[e[t]], __popc(m));
        wbase = __shfl_sync(0xffffffffu, wbase, leader);
        g_sidx[e[t] * CAP + sb[e[t]] + wbase + rank] = base + t * 256 + tid;
    }

    // Last block builds tile map
    __threadfence();
    __syncthreads();
    __shared__ int is_last;
    if (tid == 0) is_last = (atomicAdd(&g_done, 1) == gridDim.x - 1) ? 1 : 0;
    __syncthreads();
    if (!is_last) return;

    __shared__ int cnt[NEXP], toff[NEXP + 1];
    if (tid < NEXP) cnt[tid] = g_cur[tid * CSTRIDE];
    __syncthreads();
    if (tid == 0) {
        int o = 0;
        for (int ee = 0; ee < NEXP; ee++) {
            toff[ee] = o;
            o += (cnt[ee] + SPB - 1) / SPB;
        }
        toff[NEXP] = o;
    }
    __syncthreads();
    for (int b = tid; b < MAXBLK; b += 256) g_bmap[b] = -1;
    if (tid < NEXP) g_cnt[tid] = cnt[tid];
    __syncthreads();
    if (tid < NEXP) {
        int ntile = toff[tid + 1] - toff[tid];
        for (int t = 0; t < ntile; t++)
            g_bmap[toff[tid] + t] = (tid << 16) | t;
    }
}

// ---------------- K2: expert-uniform fused MLP (8 chains/thread, packed weights) ----------------
__global__ void __launch_bounds__(TPB, 4) k_mlp(const float2* __restrict__ s,
                                                const float* __restrict__ W1,
                                                const float* __restrict__ b1,
                                                const float* __restrict__ W2,
                                                const float* __restrict__ b2,
                                                float* __restrict__ out) {
    int v = g_bmap[blockIdx.x];
    // packed weights: per hidden pair p (12 floats = 3 x ulonglong2):
    // [w0lo w0hi | w1lo w1hi | bblo bbhi | v0lo v0hi | v1lo v1hi | v2lo v2hi]
    __shared__ float sw[128 * 12];

    if (v >= 0) {
        int e    = v >> 16;
        int tile = v & 0xffff;

        {
            int p = threadIdx.x;   // TPB == 128 == number of hidden pairs
            int h = 2 * p;
            sw[p * 12 + 0]  = W1[e * 512 + h];
            sw[p * 12 + 1]  = W1[e * 512 + h + 1];
            sw[p * 12 + 2]  = W1[e * 512 + 256 + h];
            sw[p * 12 + 3]  = W1[e * 512 + 256 + h + 1];
            sw[p * 12 + 4]  = b1[e * 256 + h];
            sw[p * 12 + 5]  = b1[e * 256 + h + 1];
            sw[p * 12 + 6]  = W2[(e * 256 + h) * 3 + 0];
            sw[p * 12 + 7]  = W2[(e * 256 + h + 1) * 3 + 0];
            sw[p * 12 + 8]  = W2[(e * 256 + h) * 3 + 1];
            sw[p * 12 + 9]  = W2[(e * 256 + h + 1) * 3 + 1];
            sw[p * 12 + 10] = W2[(e * 256 + h) * 3 + 2];
            sw[p * 12 + 11] = W2[(e * 256 + h + 1) * 3 + 2];
        }
        int rbase = e * CAP + tile * SPB;
        int rend  = e * CAP + g_cnt[e];
        __syncthreads();

        u64 xx0[SPT], xx1[SPT];
        #pragma unroll
        for (int t = 0; t < SPT; t++) {
            int slot = rbase + t * TPB + threadIdx.x;
            int idx  = (slot < rend) ? g_sidx[slot] : 0;
            float2 xy = __ldg(&s[idx]);
            xx0[t] = f2pack(xy.x, xy.x);
            xx1[t] = f2pack(xy.y, xy.y);
        }

        u64 acc0[SPT], acc1[SPT], acc2[SPT];
        #pragma unroll
        for (int t = 0; t < SPT; t++) { acc0[t] = 0ull; acc1[t] = 0ull; acc2[t] = 0ull; }

        const ulonglong2* swq = (const ulonglong2*)sw;
        #pragma unroll 8
        for (int p = 0; p < 128; p++) {
            ulonglong2 q0 = swq[p * 3 + 0];   // w0, w1
            ulonglong2 q1 = swq[p * 3 + 1];   // bb, v0
            ulonglong2 q2 = swq[p * 3 + 2];   // v1, v2
            #pragma unroll
            for (int t = 0; t < SPT; t++) {
                u64 h = f2fma(xx0[t], q0.x, f2fma(xx1[t], q0.y, q1.x));
                h = f2relu(h);
                acc0[t] = f2fma(h, q1.y, acc0[t]);
                acc1[t] = f2fma(h, q2.x, acc1[t]);
                acc2[t] = f2fma(h, q2.y, acc2[t]);
            }
        }

        float c0 = __ldg(&b2[e * 3 + 0]);
        float c1 = __ldg(&b2[e * 3 + 1]);
        float c2 = __ldg(&b2[e * 3 + 2]);
        #pragma unroll
        for (int t = 0; t < SPT; t++) {
            int slot = rbase + t * TPB + threadIdx.x;
            if (slot >= rend) continue;
            int idx = g_sidx[slot];           // L1 hit (read in prologue)
            float2 a0 = f2unpack(acc0[t]);
            float2 a1 = f2unpack(acc1[t]);
            float2 a2 = f2unpack(acc2[t]);
            float* o = out + (size_t)idx * 3;
            o[0] = a0.x + a0.y + c0;
            o[1] = a1.x + a1.y + c1;
            o[2] = a2.x + a2.y + c2;
        }
    }

    // per-replay state reset: last block to finish clears cursors/tickets
    if (threadIdx.x == 0) {
        __threadfence();
        if (atomicAdd(&g_fin, 1) == (int)gridDim.x - 1) {
            g_fin  = 0;
            g_done = 0;
            #pragma unroll
            for (int ee = 0; ee < NEXP; ee++) g_cur[ee * CSTRIDE] = 0;
        }
    }
}

// ---------------- launch ----------------
extern "C" void kernel_launch(void* const* d_in, const int* in_sizes, int n_in,
                              void* d_out, int out_size) {
    const float* samples = (const float*)d_in[0];
    const float* W1      = (const float*)d_in[1];
    const float* b1      = (const float*)d_in[2];
    const float* W2      = (const float*)d_in[3];
    const float* b2      = (const float*)d_in[4];
    float* out           = (float*)d_out;

    k_scatter<<<SBLK, 256>>>((const float2*)samples);
    k_mlp<<<MAXBLK, TPB>>>((const float2*)samples, W1, b1, W2, b2, out);
}